// round 1
// baseline (speedup 1.0000x reference)
#include <cuda_runtime.h>
#include <math.h>

// Problem constants: B=2, L=128, H=768, C=6, nhops=2
#define LDX   1568      // padded K (1554 -> 1568, multiple of 16)
#define MROWS 576       // padded M (513 -> 576, multiple of 64)
#define NROWS 513       // 256 P-rows + 256 Q-rows + 1 R-row
#define KF    1536      // 2H feature width
#define KE    1554      // 2H + 3C extended width
#define NC    6
#define LL    128
#define BB    2

// Scratch (allocation-free: __device__ globals)
__device__ float g_Xa[MROWS * LDX];     // ping buffer: [features(1536) | pooled(6) | pooledT(6) | probs(6) | pad]
__device__ float g_Xb[MROWS * LDX];     // pong buffer
__device__ float g_W [LDX   * KF];      // feat_w padded 1554->1568 rows with zeros
__device__ float g_pqr[NROWS * NC];     // rows 0..255: p(b,i); 256..511: q(b,j); 512: r
__device__ float g_pooled[BB * LL * NC];

// ---- pad feat_w (1554x1536) into g_W (1568x1536), zero tail rows ----
__global__ void k_padw(const float* __restrict__ feat_w) {
    int idx = blockIdx.x * 256 + threadIdx.x;        // over 1568*1536
    int k = idx / KF, n = idx - k * KF;
    g_W[idx] = (k < KE) ? feat_w[k * KF + n] : 0.f;
}

// ---- init Xa feature part from hidden; zero padding rows of both buffers ----
__global__ void k_init(const float* __restrict__ hidden) {
    int row = blockIdx.x;                            // 0..575
    float* xa = g_Xa + row * LDX;
    float* xb = g_Xb + row * LDX;
    for (int c = threadIdx.x; c < LDX; c += 256) {
        float v = 0.f;
        if (row < 256)      { if (c < 768) v = hidden[row * 768 + c]; }
        else if (row < 512) { if (c >= 768 && c < 1536) v = hidden[(row - 256) * 768 + c - 768]; }
        xa[c] = v;
        if (row >= NROWS) xb[c] = 0.f;               // keep pad rows exactly zero forever
    }
}

// ---- pqr[row,c] = X[row, 0:1536] . cls_w[:, c]  (+cls_b on the constant row) ----
__global__ void k_probs(int src, const float* __restrict__ cls_w, const float* __restrict__ cls_b) {
    const float* X = src ? g_Xb : g_Xa;
    int row  = blockIdx.x;                           // 0..512
    int warp = threadIdx.x >> 5, lane = threadIdx.x & 31;  // 6 warps = 6 channels
    const float* xr = X + row * LDX;
    float s = 0.f;
    for (int k = lane; k < KF; k += 32)
        s += xr[k] * cls_w[k * NC + warp];
    #pragma unroll
    for (int o = 16; o; o >>= 1) s += __shfl_down_sync(0xffffffffu, s, o);
    if (lane == 0) {
        if (row == 512) s += cls_b[warp];
        g_pqr[row * NC + warp] = s;
    }
}

// ---- exact masked max-pool on separable probs: pooled[b,k,c] ----
__global__ void k_pool(const float* __restrict__ am) {
    int idx = blockIdx.x * 256 + threadIdx.x;        // 0..1535 exact
    int c = idx % NC;
    int k = (idx / NC) % LL;
    int b = idx / (NC * LL);
    const float* p = g_pqr;                          // p rows
    const float* q = g_pqr + 256 * NC;               // q rows
    float r  = g_pqr[512 * NC + c];
    const float* m = am + b * LL;
    float mk = m[k];
    float pk = p[(b * LL + k) * NC + c];
    float qk = q[(b * LL + k) * NC + c];
    float mx = -INFINITY;
    // column k: lm[i,k] = (p_i + q_k + r) * (i<=k ? m_i*m_k : 0), max over all i
    for (int i = 0; i < LL; i++) {
        float mv = (i <= k) ? m[i] * mk : 0.f;
        mx = fmaxf(mx, (p[(b * LL + i) * NC + c] + qk + r) * mv);
    }
    // row k: lm[k,j] = (p_k + q_j + r) * (j>=k ? m_k*m_j : 0), max over all j
    for (int j = 0; j < LL; j++) {
        float mv = (j >= k) ? mk * m[j] : 0.f;
        mx = fmaxf(mx, (pk + q[(b * LL + j) * NC + c] + r) * mv);
    }
    g_pooled[idx] = mx;
}

// ---- write extended 18 cols (+14 zero pad cols) of X for this hop ----
__global__ void k_ext(int src) {
    float* X = src ? g_Xb : g_Xa;
    int row = blockIdx.x;                            // 0..512
    int t   = threadIdx.x;                           // 0..31
    float v = 0.f;
    if (t < 18) {
        if (row < 256) {                             // P rows: [pooled_i, 0, p_i]
            if (t < 6)        v = g_pooled[row * NC + t];
            else if (t >= 12) v = g_pqr[row * NC + t - 12];
        } else if (row < 512) {                      // Q rows: [0, pooled_j, q_j]
            if (t >= 6 && t < 12) v = g_pooled[(row - 256) * NC + t - 6];
            else if (t >= 12)     v = g_pqr[row * NC + t - 12];
        } else {                                     // R row: [0, 0, r]
            if (t >= 12) v = g_pqr[row * NC + t - 12];
        }
    }
    X[row * LDX + 1536 + t] = v;
}

// ---- the hop GEMM: C(dst)[:, 0:1536] = A(src)[576 x 1568] @ g_W[1568 x 1536]; row 512 += feat_b ----
__global__ void __launch_bounds__(256) k_gemm(int src, const float* __restrict__ bias) {
    const float* A = src ? g_Xb : g_Xa;
    float*       C = src ? g_Xa : g_Xb;
    __shared__ float As[16][64];                     // transposed A tile: As[k][m]
    __shared__ float Bs[16][64];
    int bm = blockIdx.y * 64, bn = blockIdx.x * 64;
    int tid  = threadIdx.x;
    int tx   = tid & 15, ty = tid >> 4;
    int arow = tid >> 2, acol = (tid & 3) << 2;      // A load: 64 rows x 4 float-cols
    int brow = tid >> 4, bcol = (tid & 15) << 2;     // B load: 16 rows x 16 float4-cols
    float acc[4][4];
    #pragma unroll
    for (int i = 0; i < 4; i++)
        #pragma unroll
        for (int j = 0; j < 4; j++) acc[i][j] = 0.f;

    const float* Ap = A + (bm + arow) * LDX + acol;
    const float* Bp = g_W + brow * KF + bn + bcol;

    for (int k0 = 0; k0 < LDX; k0 += 16) {           // 98 k-tiles
        float4 a = *(const float4*)(Ap + k0);
        float4 b = *(const float4*)(Bp + (size_t)k0 * KF);
        __syncthreads();
        As[acol + 0][arow] = a.x;
        As[acol + 1][arow] = a.y;
        As[acol + 2][arow] = a.z;
        As[acol + 3][arow] = a.w;
        *(float4*)&Bs[brow][bcol] = b;
        __syncthreads();
        #pragma unroll
        for (int kk = 0; kk < 16; kk++) {
            float4 ra = *(const float4*)&As[kk][ty << 2];
            float4 rb = *(const float4*)&Bs[kk][tx << 2];
            float ras[4] = {ra.x, ra.y, ra.z, ra.w};
            float rbs[4] = {rb.x, rb.y, rb.z, rb.w};
            #pragma unroll
            for (int i = 0; i < 4; i++)
                #pragma unroll
                for (int j = 0; j < 4; j++)
                    acc[i][j] += ras[i] * rbs[j];
        }
    }
    int cbase = bn + (tx << 2);
    #pragma unroll
    for (int i = 0; i < 4; i++) {
        int r = bm + (ty << 2) + i;
        float4 o;
        o.x = acc[i][0]; o.y = acc[i][1]; o.z = acc[i][2]; o.w = acc[i][3];
        if (r == 512) {                              // feat_b goes into the constant row only
            o.x += bias[cbase]; o.y += bias[cbase + 1];
            o.z += bias[cbase + 2]; o.w += bias[cbase + 3];
        }
        *(float4*)(C + r * LDX + cbase) = o;
    }
}

// ---- final: logits[b,i,j,c] = p[b,i,c] + q[b,j,c] + r[c] ----
__global__ void k_out(float* __restrict__ out) {
    int idx = blockIdx.x * 256 + threadIdx.x;        // 0..196607 exact
    int c = idx % NC;
    int j = (idx / NC) % LL;
    int t = idx / (NC * LL);
    int i = t % LL;
    int b = t / LL;
    out[idx] = g_pqr[(b * LL + i) * NC + c]
             + g_pqr[(256 + b * LL + j) * NC + c]
             + g_pqr[512 * NC + c];
}

extern "C" void kernel_launch(void* const* d_in, const int* in_sizes, int n_in,
                              void* d_out, int out_size) {
    const float* hidden = (const float*)d_in[0];
    const float* am     = (const float*)d_in[1];
    const float* cls_w  = (const float*)d_in[2];
    const float* cls_b  = (const float*)d_in[3];
    const float* feat_w = (const float*)d_in[4];
    const float* feat_b = (const float*)d_in[5];
    // d_in[6] = nhops (always 2 in this dataset)

    k_padw<<<(LDX * KF) / 256, 256>>>(feat_w);
    k_init<<<MROWS, 256>>>(hidden);
    k_probs<<<NROWS, 192>>>(0, cls_w, cls_b);        // probs0 from Xa features

    for (int h = 0; h < 2; h++) {
        int src = h & 1;                             // hop0: Xa->Xb, hop1: Xb->Xa
        k_pool<<<6, 256>>>(am);
        k_ext<<<NROWS, 32>>>(src);
        k_gemm<<<dim3(24, 9), 256>>>(src, feat_b);
        k_probs<<<NROWS, 192>>>(1 - src, cls_w, cls_b);
    }
    k_out<<<768, 256>>>((float*)d_out);
}

// round 2
// speedup vs baseline: 1.7358x; 1.7358x over previous
#include <cuda_runtime.h>
#include <math.h>

// Problem constants: B=2, L=128, H=768, C=6, nhops=2
#define LDX   1568      // padded K (1554 -> 1568, multiple of 32)
#define MROWS 576       // padded M (513 -> 576, multiple of 96)
#define NROWS 513       // 256 P-rows + 256 Q-rows + 1 R-row
#define KF    1536      // 2H feature width
#define KE    1554      // 2H + 3C extended width
#define NC    6
#define LL    128

#define PADA  98        // As row pitch (floats): even (8B-aligned LDS.64), 2-way-max STS
#define PADB  68        // Bs row pitch (floats)

typedef unsigned long long ull;

// Scratch (allocation-free: __device__ globals)
__device__ float g_Xa[MROWS * LDX];
__device__ float g_Xb[MROWS * LDX];
__device__ float g_W [LDX   * KF];      // feat_w padded 1554->1568 rows with zeros
__device__ float g_clsT[NC * KF];       // cls_w transposed [c][k]
__device__ float g_pqr[NROWS * NC];     // 0..255: p(b,i); 256..511: q(b,j); 512: r
__device__ float g_pooled[2 * LL * NC];

// ---- pad feat_w into g_W; also build transposed cls_w ----
__global__ void k_padw(const float* __restrict__ feat_w, const float* __restrict__ cls_w) {
    int idx = blockIdx.x * 256 + threadIdx.x;
    if (idx < LDX * KF) {
        int k = idx / KF, n = idx - k * KF;
        g_W[idx] = (k < KE) ? feat_w[k * KF + n] : 0.f;
    } else {
        int t = idx - LDX * KF;
        if (t < NC * KF) {
            int c = t / KF, k = t - c * KF;
            g_clsT[t] = cls_w[k * NC + c];
        }
    }
}

// ---- init Xa feature part from hidden; zero pad rows of both buffers ----
__global__ void k_init(const float* __restrict__ hidden) {
    int row = blockIdx.x;                            // 0..575
    float* xa = g_Xa + row * LDX;
    float* xb = g_Xb + row * LDX;
    for (int c = threadIdx.x; c < LDX; c += 256) {
        float v = 0.f;
        if (row < 256)      { if (c < 768) v = hidden[row * 768 + c]; }
        else if (row < 512) { if (c >= 768 && c < 1536) v = hidden[(row - 256) * 768 + c - 768]; }
        xa[c] = v;
        if (row >= NROWS) xb[c] = 0.f;
    }
}

// ---- pqr[row,c] = X[row, 0:1536] . cls_w[:, c]  (+cls_b on constant row) ----
__global__ void k_probs(int src, const float* __restrict__ cls_b) {
    const float* X = src ? g_Xb : g_Xa;
    int row  = blockIdx.x;                           // 0..512
    int warp = threadIdx.x >> 5, lane = threadIdx.x & 31;  // 6 warps = 6 channels
    const float4* xr = (const float4*)(X + row * LDX);
    const float4* wr = (const float4*)(g_clsT + warp * KF);
    float s = 0.f;
    #pragma unroll
    for (int it = 0; it < 12; it++) {                // 12*32*4 = 1536
        int k4 = it * 32 + lane;
        float4 a = xr[k4], b = wr[k4];
        s += a.x * b.x + a.y * b.y + a.z * b.z + a.w * b.w;
    }
    #pragma unroll
    for (int o = 16; o; o >>= 1) s += __shfl_down_sync(0xffffffffu, s, o);
    if (lane == 0) {
        if (row == 512) s += cls_b[warp];
        g_pqr[row * NC + warp] = s;
    }
}

// ---- exact masked max-pool, one warp per output element ----
__global__ void k_pool(const float* __restrict__ am) {
    int gw   = blockIdx.x * 8 + (threadIdx.x >> 5);  // 0..1535
    int lane = threadIdx.x & 31;
    int c = gw % NC;
    int k = (gw / NC) % LL;
    int b = gw / (NC * LL);
    const float* p = g_pqr;
    const float* q = g_pqr + 256 * NC;
    float r  = g_pqr[512 * NC + c];
    const float* m = am + b * LL;
    float mk = m[k];
    float pk = p[(b * LL + k) * NC + c];
    float qk = q[(b * LL + k) * NC + c];
    float mx = -INFINITY;
    #pragma unroll
    for (int u = 0; u < 4; u++) {
        int i = lane + u * 32;
        float mi = m[i];
        float mv1 = (i <= k) ? mi * mk : 0.f;        // column k over i
        mx = fmaxf(mx, (p[(b * LL + i) * NC + c] + qk + r) * mv1);
        float mv2 = (i >= k) ? mk * mi : 0.f;        // row k over j
        mx = fmaxf(mx, (pk + q[(b * LL + i) * NC + c] + r) * mv2);
    }
    #pragma unroll
    for (int o = 16; o; o >>= 1) mx = fmaxf(mx, __shfl_down_sync(0xffffffffu, mx, o));
    if (lane == 0) g_pooled[gw] = mx;
}

// ---- write extended 18 cols (+14 zero pad) of X for this hop ----
__global__ void k_ext(int src) {
    float* X = src ? g_Xb : g_Xa;
    int row = blockIdx.x;                            // 0..512
    int t   = threadIdx.x;                           // 0..31
    float v = 0.f;
    if (t < 18) {
        if (row < 256) {
            if (t < 6)        v = g_pooled[row * NC + t];
            else if (t >= 12) v = g_pqr[row * NC + t - 12];
        } else if (row < 512) {
            if (t >= 6 && t < 12) v = g_pooled[(row - 256) * NC + t - 6];
            else if (t >= 12)     v = g_pqr[row * NC + t - 12];
        } else {
            if (t >= 12) v = g_pqr[row * NC + t - 12];
        }
    }
    X[row * LDX + 1536 + t] = v;
}

// ---- hop GEMM with packed f32x2 FMAs: C[576x1536] = A[576x1568] @ W[1568x1536] ----
// 96x64 tiles, grid (24,6)=144 blocks = one wave. 6x4 microtile, M-paired FFMA2.
__global__ void __launch_bounds__(256, 1) k_gemm(int src, const float* __restrict__ bias) {
    const float* __restrict__ A = src ? g_Xb : g_Xa;
    float*       __restrict__ C = src ? g_Xa : g_Xb;

    __shared__ float As[2][32 * PADA];               // transposed: As[k][m]
    __shared__ float Bs[2][32 * PADB];

    const int bm = blockIdx.y * 96, bn = blockIdx.x * 64;
    const int tid = threadIdx.x;
    const int tx = tid & 15, ty = tid >> 4;          // col group / row group

    // A load mapping: 3 float4 per thread (96 rows x 8 float4-cols)
    const int ar0 = tid >> 3,        ac0 = (tid & 7) << 2;
    const int ar1 = (tid + 256) >> 3, ac1 = ((tid + 256) & 7) << 2;
    const int ar2 = (tid + 512) >> 3, ac2 = ((tid + 512) & 7) << 2;
    // B load mapping: 2 float4 per thread (32 rows x 16 float4-cols)
    const int br0 = tid >> 4,        bc0 = (tid & 15) << 2;
    const int br1 = (tid + 256) >> 4, bc1 = ((tid + 256) & 15) << 2;

    ull acc[4][3];                                   // acc[j][ip] = (C[2ip], C[2ip+1]) pair
    #pragma unroll
    for (int j = 0; j < 4; j++)
        #pragma unroll
        for (int ip = 0; ip < 3; ip++) acc[j][ip] = 0ull;

    float4 a0, a1, a2, b0, b1;
    // prologue: load ktile 0
    a0 = *(const float4*)(A + (bm + ar0) * LDX + ac0);
    a1 = *(const float4*)(A + (bm + ar1) * LDX + ac1);
    a2 = *(const float4*)(A + (bm + ar2) * LDX + ac2);
    b0 = *(const float4*)(g_W + (size_t)br0 * KF + bn + bc0);
    b1 = *(const float4*)(g_W + (size_t)br1 * KF + bn + bc1);
    {
        float* as = As[0]; float* bs = Bs[0];
        as[(ac0+0)*PADA+ar0]=a0.x; as[(ac0+1)*PADA+ar0]=a0.y; as[(ac0+2)*PADA+ar0]=a0.z; as[(ac0+3)*PADA+ar0]=a0.w;
        as[(ac1+0)*PADA+ar1]=a1.x; as[(ac1+1)*PADA+ar1]=a1.y; as[(ac1+2)*PADA+ar1]=a1.z; as[(ac1+3)*PADA+ar1]=a1.w;
        as[(ac2+0)*PADA+ar2]=a2.x; as[(ac2+1)*PADA+ar2]=a2.y; as[(ac2+2)*PADA+ar2]=a2.z; as[(ac2+3)*PADA+ar2]=a2.w;
        *(float4*)(bs + br0*PADB + bc0) = b0;
        *(float4*)(bs + br1*PADB + bc1) = b1;
    }

    const int NT = LDX / 32;                         // 49 k-tiles
    int buf = 0;
    for (int t = 0; t < NT; t++) {
        __syncthreads();                             // smem[buf] ready
        if (t + 1 < NT) {                            // prefetch next tile into regs
            int k0 = (t + 1) * 32;
            a0 = *(const float4*)(A + (bm + ar0) * LDX + k0 + ac0);
            a1 = *(const float4*)(A + (bm + ar1) * LDX + k0 + ac1);
            a2 = *(const float4*)(A + (bm + ar2) * LDX + k0 + ac2);
            b0 = *(const float4*)(g_W + (size_t)(k0 + br0) * KF + bn + bc0);
            b1 = *(const float4*)(g_W + (size_t)(k0 + br1) * KF + bn + bc1);
        }
        const float* as = As[buf];
        const float* bs = Bs[buf];
        #pragma unroll 16
        for (int kk = 0; kk < 32; kk++) {
            const float* ap = as + kk * PADA + ty * 6;
            ull p0 = *(const ull*)(ap + 0);
            ull p1 = *(const ull*)(ap + 2);
            ull p2 = *(const ull*)(ap + 4);
            float4 bv = *(const float4*)(bs + kk * PADB + (tx << 2));
            ull q0, q1, q2, q3;
            asm("mov.b64 %0,{%1,%1};" : "=l"(q0) : "f"(bv.x));
            asm("mov.b64 %0,{%1,%1};" : "=l"(q1) : "f"(bv.y));
            asm("mov.b64 %0,{%1,%1};" : "=l"(q2) : "f"(bv.z));
            asm("mov.b64 %0,{%1,%1};" : "=l"(q3) : "f"(bv.w));
            asm("fma.rn.f32x2 %0,%1,%2,%0;" : "+l"(acc[0][0]) : "l"(p0), "l"(q0));
            asm("fma.rn.f32x2 %0,%1,%2,%0;" : "+l"(acc[0][1]) : "l"(p1), "l"(q0));
            asm("fma.rn.f32x2 %0,%1,%2,%0;" : "+l"(acc[0][2]) : "l"(p2), "l"(q0));
            asm("fma.rn.f32x2 %0,%1,%2,%0;" : "+l"(acc[1][0]) : "l"(p0), "l"(q1));
            asm("fma.rn.f32x2 %0,%1,%2,%0;" : "+l"(acc[1][1]) : "l"(p1), "l"(q1));
            asm("fma.rn.f32x2 %0,%1,%2,%0;" : "+l"(acc[1][2]) : "l"(p2), "l"(q1));
            asm("fma.rn.f32x2 %0,%1,%2,%0;" : "+l"(acc[2][0]) : "l"(p0), "l"(q2));
            asm("fma.rn.f32x2 %0,%1,%2,%0;" : "+l"(acc[2][1]) : "l"(p1), "l"(q2));
            asm("fma.rn.f32x2 %0,%1,%2,%0;" : "+l"(acc[2][2]) : "l"(p2), "l"(q2));
            asm("fma.rn.f32x2 %0,%1,%2,%0;" : "+l"(acc[3][0]) : "l"(p0), "l"(q3));
            asm("fma.rn.f32x2 %0,%1,%2,%0;" : "+l"(acc[3][1]) : "l"(p1), "l"(q3));
            asm("fma.rn.f32x2 %0,%1,%2,%0;" : "+l"(acc[3][2]) : "l"(p2), "l"(q3));
        }
        if (t + 1 < NT) {                            // store prefetched tile to other buffer
            float* asw = As[buf ^ 1]; float* bsw = Bs[buf ^ 1];
            asw[(ac0+0)*PADA+ar0]=a0.x; asw[(ac0+1)*PADA+ar0]=a0.y; asw[(ac0+2)*PADA+ar0]=a0.z; asw[(ac0+3)*PADA+ar0]=a0.w;
            asw[(ac1+0)*PADA+ar1]=a1.x; asw[(ac1+1)*PADA+ar1]=a1.y; asw[(ac1+2)*PADA+ar1]=a1.z; asw[(ac1+3)*PADA+ar1]=a1.w;
            asw[(ac2+0)*PADA+ar2]=a2.x; asw[(ac2+1)*PADA+ar2]=a2.y; asw[(ac2+2)*PADA+ar2]=a2.z; asw[(ac2+3)*PADA+ar2]=a2.w;
            *(float4*)(bsw + br0*PADB + bc0) = b0;
            *(float4*)(bsw + br1*PADB + bc1) = b1;
        }
        buf ^= 1;
    }

    // epilogue: unpack pairs, add bias on the constant row, write
    const int cbase = bn + (tx << 2);
    #pragma unroll
    for (int ip = 0; ip < 3; ip++) {
        #pragma unroll
        for (int h = 0; h < 2; h++) {
            int r = bm + ty * 6 + ip * 2 + h;
            float4 o;
            o.x = __uint_as_float(h ? (unsigned)(acc[0][ip] >> 32) : (unsigned)acc[0][ip]);
            o.y = __uint_as_float(h ? (unsigned)(acc[1][ip] >> 32) : (unsigned)acc[1][ip]);
            o.z = __uint_as_float(h ? (unsigned)(acc[2][ip] >> 32) : (unsigned)acc[2][ip]);
            o.w = __uint_as_float(h ? (unsigned)(acc[3][ip] >> 32) : (unsigned)acc[3][ip]);
            if (r == 512) {
                o.x += bias[cbase]; o.y += bias[cbase + 1];
                o.z += bias[cbase + 2]; o.w += bias[cbase + 3];
            }
            *(float4*)(C + (size_t)r * LDX + cbase) = o;
        }
    }
}

// ---- final: logits[b,i,j,c] = p[b,i,c] + q[b,j,c] + r[c] ----
__global__ void k_out(float* __restrict__ out) {
    int idx = blockIdx.x * 256 + threadIdx.x;        // 0..196607 exact
    int c = idx % NC;
    int j = (idx / NC) % LL;
    int t = idx / (NC * LL);
    int i = t % LL;
    int b = t / LL;
    out[idx] = g_pqr[(b * LL + i) * NC + c]
             + g_pqr[(256 + b * LL + j) * NC + c]
             + g_pqr[512 * NC + c];
}

extern "C" void kernel_launch(void* const* d_in, const int* in_sizes, int n_in,
                              void* d_out, int out_size) {
    const float* hidden = (const float*)d_in[0];
    const float* am     = (const float*)d_in[1];
    const float* cls_w  = (const float*)d_in[2];
    const float* cls_b  = (const float*)d_in[3];
    const float* feat_w = (const float*)d_in[4];
    const float* feat_b = (const float*)d_in[5];

    k_padw<<<(LDX * KF) / 256 + 36, 256>>>(feat_w, cls_w);
    k_init<<<MROWS, 256>>>(hidden);
    k_probs<<<NROWS, 192>>>(0, cls_b);

    for (int h = 0; h < 2; h++) {
        int src = h & 1;                             // hop0: Xa->Xb, hop1: Xb->Xa
        k_pool<<<192, 256>>>(am);
        k_ext<<<NROWS, 32>>>(src);
        k_gemm<<<dim3(24, 6), 256>>>(src, feat_b);
        k_probs<<<NROWS, 192>>>(1 - src, cls_b);
    }
    k_out<<<768, 256>>>((float*)d_out);
}

// round 5
// speedup vs baseline: 2.2245x; 1.2815x over previous
#include <cuda_runtime.h>
#include <cuda_bf16.h>
#include <math.h>

// Problem constants: B=2, L=128, H=768, C=6, nhops=2
#define LDX 1568
#define NC  6
#define LL  128
#define KP  1600     // padded K (1554 -> 1600)
#define MP  640      // padded M (513 -> 640)
#define NF  1536     // output feature width

typedef unsigned int u32;
typedef unsigned short u16;

// Scratch (allocation-free: __device__ globals)
__device__ __align__(16) float g_Xa[513 * LDX];
__device__ __align__(16) float g_Xb[513 * LDX];
__device__ __align__(16) __nv_bfloat16 g_A[2][2][MP * KP];   // [set][hi/lo], row-major [MP][KP]
__device__ __align__(16) __nv_bfloat16 g_Wt[2][NF * KP];     // [hi/lo], W^T: row n, col k
__device__ __align__(16) float g_clsT[NC * 1536];
__device__ float g_pqr[513 * NC];        // 0..255 p, 256..511 q, 512 r
__device__ float g_pooled[2 * LL * NC];

__device__ __forceinline__ void bsplit(float v, u16& h, u16& l) {
    __nv_bfloat16 hb = __float2bfloat16(v);
    __nv_bfloat16 lb = __float2bfloat16(v - __bfloat162float(hb));
    h = *(u16*)&hb; l = *(u16*)&lb;
}
__device__ __forceinline__ u32 smem_u32(const void* p) {
    u32 a;
    asm("{ .reg .u64 t; cvta.to.shared.u64 t, %1; cvt.u32.u64 %0, t; }" : "=r"(a) : "l"(p));
    return a;
}
__device__ __forceinline__ void cpa16(u32 s, const void* g) {
    asm volatile("cp.async.cg.shared.global [%0], [%1], 16;" :: "r"(s), "l"(g));
}
__device__ __forceinline__ u32 lds32(u32 a) {
    u32 x; asm volatile("ld.shared.b32 %0, [%1];" : "=r"(x) : "r"(a)); return x;
}
__device__ __forceinline__ void mma16816(float* c, const u32* a, u32 b0, u32 b1) {
    asm volatile("mma.sync.aligned.m16n8k16.row.col.f32.bf16.bf16.f32 "
        "{%0,%1,%2,%3},{%4,%5,%6,%7},{%8,%9},{%0,%1,%2,%3};"
        : "+f"(c[0]), "+f"(c[1]), "+f"(c[2]), "+f"(c[3])
        : "r"(a[0]), "r"(a[1]), "r"(a[2]), "r"(a[3]), "r"(b0), "r"(b1));
}

// ---------------- one-time: transpose+split feat_w -> g_Wt ----------------
__global__ void k_convW(const float* __restrict__ feat_w) {
    __shared__ float ts[32][33];
    int bk = blockIdx.x, bn = blockIdx.y;            // k tile 0..49, n tile 0..47
    int tx = threadIdx.x, ty = threadIdx.y;          // 32 x 8
    #pragma unroll
    for (int i = 0; i < 32; i += 8) {
        int k = bk * 32 + ty + i;
        ts[ty + i][tx] = (k < 1554) ? feat_w[(size_t)k * 1536 + bn * 32 + tx] : 0.f;
    }
    __syncthreads();
    #pragma unroll
    for (int i = 0; i < 32; i += 8) {
        int n = bn * 32 + ty + i;
        int k = bk * 32 + tx;
        u16 h, l; bsplit(ts[tx][ty + i], h, l);
        *(u16*)&g_Wt[0][(size_t)n * KP + k] = h;
        *(u16*)&g_Wt[1][(size_t)n * KP + k] = l;
    }
}

// ---------------- one-time: transposed cls_w ----------------
__global__ void k_cls(const float* __restrict__ cls_w) {
    int t = blockIdx.x * 256 + threadIdx.x;
    if (t < NC * 1536) {
        int c = t / 1536, k = t % 1536;
        g_clsT[t] = cls_w[k * NC + c];
    }
}

// ---------------- init: X fp32 + A set0 bf16 (+ zero pad rows of set1) ----------------
__global__ void k_init(const float* __restrict__ hidden) {
    int row = blockIdx.x;                            // 0..639
    for (int c = threadIdx.x; c < KP; c += 256) {
        float v = 0.f;
        if (row < 256)      { if (c < 768) v = hidden[row * 768 + c]; }
        else if (row < 512) { if (c >= 768 && c < 1536) v = hidden[(row - 256) * 768 + c - 768]; }
        if (row < 513 && c < LDX) g_Xa[(size_t)row * LDX + c] = v;
        u16 h, l; bsplit(v, h, l);
        *(u16*)&g_A[0][0][(size_t)row * KP + c] = h;
        *(u16*)&g_A[0][1][(size_t)row * KP + c] = l;
        if (row >= 513) {                            // pad rows of set1 stay zero forever
            *(u16*)&g_A[1][0][(size_t)row * KP + c] = 0;
            *(u16*)&g_A[1][1][(size_t)row * KP + c] = 0;
        }
    }
}

// ---------------- pqr[row,c] = X[row,0:1536] . cls_w[:,c] (+cls_b on row 512) ----------------
__global__ void k_probs(int src, const float* __restrict__ cls_b) {
    const float* X = src ? g_Xb : g_Xa;
    int row  = blockIdx.x;                           // 0..512
    int warp = threadIdx.x >> 5, lane = threadIdx.x & 31;
    const float4* xr = (const float4*)(X + (size_t)row * LDX);
    const float4* wr = (const float4*)(g_clsT + warp * 1536);
    float s = 0.f;
    #pragma unroll
    for (int it = 0; it < 12; it++) {
        int k4 = it * 32 + lane;
        float4 a = xr[k4], b = wr[k4];
        s += a.x * b.x + a.y * b.y + a.z * b.z + a.w * b.w;
    }
    #pragma unroll
    for (int o = 16; o; o >>= 1) s += __shfl_down_sync(0xffffffffu, s, o);
    if (lane == 0) {
        if (row == 512) s += cls_b[warp];
        g_pqr[row * NC + warp] = s;
    }
}

// ---------------- exact masked max-pool on separable probs ----------------
__global__ void k_pool(const float* __restrict__ am) {
    int b = blockIdx.x / NC, c = blockIdx.x % NC;    // 12 blocks
    __shared__ float sp[LL], sq[LL], sm[LL];
    int k = threadIdx.x;                             // 128 threads
    sp[k] = g_pqr[(b * LL + k) * NC + c];
    sq[k] = g_pqr[(256 + b * LL + k) * NC + c];
    sm[k] = am[b * LL + k];
    __syncthreads();
    float r  = g_pqr[512 * NC + c];
    float mk = sm[k], pk = sp[k], qk = sq[k];
    float mx = -INFINITY;
    #pragma unroll 4
    for (int i = 0; i < LL; i++) {
        float mi  = sm[i];
        float mv1 = (i <= k) ? mi * mk : 0.f;        // column k over i
        mx = fmaxf(mx, (sp[i] + qk + r) * mv1);
        float mv2 = (i >= k) ? mk * mi : 0.f;        // row k over j
        mx = fmaxf(mx, (pk + sq[i] + r) * mv2);
    }
    g_pooled[(b * LL + k) * NC + c] = mx;
}

// ---------------- extended column value ----------------
__device__ __forceinline__ float extval(int R, int t) {
    if (t >= 18) return 0.f;
    if (t < 6)  return (R < 256) ? g_pooled[R * NC + t] : 0.f;
    if (t < 12) return (R >= 256 && R < 512) ? g_pooled[(R - 256) * NC + t - 6] : 0.f;
    return g_pqr[R * NC + t - 12];
}

// ---------------- per-hop: fill ext cols 1536..1599 of A[set], rows 0..512 ----------------
__global__ void k_ext(int set) {
    int idx = blockIdx.x * 256 + threadIdx.x;
    if (idx >= 513 * 64) return;
    int row = idx >> 6, cc = idx & 63;
    float v = (cc < 18) ? extval(row, cc) : 0.f;
    u16 h, l; bsplit(v, h, l);
    *(u16*)&g_A[set][0][(size_t)row * KP + 1536 + cc] = h;
    *(u16*)&g_A[set][1][(size_t)row * KP + 1536 + cc] = l;
}

// ---------------- HMMA split-bf16 GEMM: C[640x1536] = A @ W^T' ----------------
// CTA 128x64, 8 warps (warp tile 64x16), 3-stage cp.async pipeline.
// Also emits next hop's bf16 hi/lo A into the other set.
#define STG 30720     // Ah 10240 | Al 10240 | Bh 5120 | Bl 5120   (pitch 80B)
__global__ void __launch_bounds__(256, 1) k_gemm(int set, const float* __restrict__ bias) {
    extern __shared__ __align__(16) char smem[];
    const __nv_bfloat16* Ah = g_A[set][0];
    const __nv_bfloat16* Al = g_A[set][1];
    __nv_bfloat16* Aoh = g_A[set ^ 1][0];
    __nv_bfloat16* Aol = g_A[set ^ 1][1];
    float* C = set ? g_Xa : g_Xb;

    const int tid = threadIdx.x;
    const int m0 = blockIdx.y * 128, n0 = blockIdx.x * 64;
    const u32 sb = smem_u32(smem);

    const int r4 = tid >> 2, q4 = (tid & 3) * 16;    // A-copy row/chunk
    const char* gAh = (const char*)Ah + (size_t)(m0 + r4) * (KP * 2) + q4;
    const char* gAl = (const char*)Al + (size_t)(m0 + r4) * (KP * 2) + q4;
    const char* gBh = (const char*)g_Wt[0] + (size_t)(n0 + r4) * (KP * 2) + q4;
    const char* gBl = (const char*)g_Wt[1] + (size_t)(n0 + r4) * (KP * 2) + q4;

    #define COPY_STAGE(s, kt) do {                                            \
        u32 d = sb + (s) * STG;                                               \
        int kb = (kt) * 64;                                                   \
        cpa16(d +         r4 * 80 + q4,        gAh + kb);                     \
        cpa16(d +         (64 + r4) * 80 + q4, gAh + kb + 64 * KP * 2);       \
        cpa16(d + 10240 + r4 * 80 + q4,        gAl + kb);                     \
        cpa16(d + 10240 + (64 + r4) * 80 + q4, gAl + kb + 64 * KP * 2);       \
        cpa16(d + 20480 + r4 * 80 + q4,        gBh + kb);                     \
        cpa16(d + 25600 + r4 * 80 + q4,        gBl + kb);                     \
        asm volatile("cp.async.commit_group;" ::: "memory");                  \
    } while (0)

    COPY_STAGE(0, 0);
    COPY_STAGE(1, 1);

    const int wid = tid >> 5, lane = tid & 31;
    const int wm = wid >> 2, wn = wid & 3;           // warp grid 2(m) x 4(n)
    const int g = lane >> 2, t = lane & 3;
    const u32 a_off = (u32)((wm * 64 + g) * 80 + t * 4);
    const u32 b_off = (u32)(20480 + (wn * 16 + g) * 80 + t * 4);

    float acc[4][2][4];
    #pragma unroll
    for (int mt = 0; mt < 4; mt++)
        #pragma unroll
        for (int nt = 0; nt < 2; nt++)
            #pragma unroll
            for (int i = 0; i < 4; i++) acc[mt][nt][i] = 0.f;

    for (int kt = 0; kt < 50; kt++) {
        if (kt < 49) asm volatile("cp.async.wait_group 1;" ::: "memory");
        else         asm volatile("cp.async.wait_group 0;" ::: "memory");
        __syncthreads();
        u32 st = sb + (kt % 3) * STG;
        #pragma unroll
        for (int kk = 0; kk < 2; kk++) {             // two k16 halves (32B each)
            u32 ka = st + a_off + kk * 32;
            u32 kb = st + b_off + kk * 32;
            u32 ah[4][4], al[4][4];
            #pragma unroll
            for (int mt = 0; mt < 4; mt++) {
                u32 base = ka + mt * 1280;           // 16 rows * 80B
                ah[mt][0] = lds32(base);
                ah[mt][1] = lds32(base + 640);       // +8 rows
                ah[mt][2] = lds32(base + 16);        // +8 k
                ah[mt][3] = lds32(base + 656);
                al[mt][0] = lds32(base + 10240);
                al[mt][1] = lds32(base + 10880);
                al[mt][2] = lds32(base + 10256);
                al[mt][3] = lds32(base + 10896);
            }
            #pragma unroll
            for (int nt = 0; nt < 2; nt++) {
                u32 bb  = kb + nt * 640;             // +8 n rows
                u32 bh0 = lds32(bb),        bh1 = lds32(bb + 16);
                u32 bl0 = lds32(bb + 5120), bl1 = lds32(bb + 5136);
                #pragma unroll
                for (int mt = 0; mt < 4; mt++) {
                    mma16816(acc[mt][nt], ah[mt], bh0, bh1);
                    mma16816(acc[mt][nt], ah[mt], bl0, bl1);
                    mma16816(acc[mt][nt], al[mt], bh0, bh1);
                }
            }
        }
        if (kt + 2 < 50) COPY_STAGE((kt + 2) % 3, kt + 2);
    }

    // epilogue: fp32 C (pitch LDX) + bf16 hi/lo A for next hop (pitch KP)
    #pragma unroll
    for (int mt = 0; mt < 4; mt++) {
        #pragma unroll
        for (int nt = 0; nt < 2; nt++) {
            int col = n0 + wn * 16 + nt * 8 + t * 2;
            #pragma unroll
            for (int half = 0; half < 2; half++) {
                int r = m0 + wm * 64 + mt * 16 + g + half * 8;
                if (r < 513) {
                    float v0 = acc[mt][nt][half * 2];
                    float v1 = acc[mt][nt][half * 2 + 1];
                    if (r == 512) { v0 += bias[col]; v1 += bias[col + 1]; }
                    float2 o; o.x = v0; o.y = v1;
                    *(float2*)(C + (size_t)r * LDX + col) = o;
                    u16 h0, l0, h1, l1;
                    bsplit(v0, h0, l0); bsplit(v1, h1, l1);
                    *(u32*)(Aoh + (size_t)r * KP + col) = (u32)h0 | ((u32)h1 << 16);
                    *(u32*)(Aol + (size_t)r * KP + col) = (u32)l0 | ((u32)l1 << 16);
                }
            }
        }
    }
    #undef COPY_STAGE
}

// ---------------- final: logits[b,i,j,c] = p[b,i,c] + q[b,j,c] + r[c] ----------------
__global__ void k_out(float* __restrict__ out) {
    int idx = blockIdx.x * 256 + threadIdx.x;        // 0..196607 exact
    int c = idx % NC;
    int j = (idx / NC) % LL;
    int t = idx / (NC * LL);
    int i = t % LL;
    int b = t / LL;
    out[idx] = g_pqr[(b * LL + i) * NC + c]
             + g_pqr[(256 + b * LL + j) * NC + c]
             + g_pqr[512 * NC + c];
}

extern "C" void kernel_launch(void* const* d_in, const int* in_sizes, int n_in,
                              void* d_out, int out_size) {
    const float* hidden = (const float*)d_in[0];
    const float* am     = (const float*)d_in[1];
    const float* cls_w  = (const float*)d_in[2];
    const float* cls_b  = (const float*)d_in[3];
    const float* feat_w = (const float*)d_in[4];
    const float* feat_b = (const float*)d_in[5];

    cudaFuncSetAttribute(k_gemm, cudaFuncAttributeMaxDynamicSharedMemorySize, 3 * STG);

    k_convW<<<dim3(50, 48), dim3(32, 8)>>>(feat_w);
    k_cls<<<36, 256>>>(cls_w);
    k_init<<<MP, 256>>>(hidden);
    k_probs<<<513, 192>>>(0, cls_b);                 // probs0 from Xa

    for (int h = 0; h < 2; h++) {
        int set = h;                                 // hop0: A set0 -> Xb + set1; hop1: set1 -> Xa + set0
        k_pool<<<12, 128>>>(am);
        k_ext<<<129, 256>>>(set);
        k_gemm<<<dim3(24, 5), 256, 3 * STG>>>(set, feat_b);
        k_probs<<<513, 192>>>(set ^ 1, cls_b);
    }
    k_out<<<768, 256>>>((float*)d_out);
}

// round 6
// speedup vs baseline: 2.2965x; 1.0324x over previous
#include <cuda_runtime.h>
#include <cuda_bf16.h>
#include <math.h>

// Problem constants: B=2, L=128, H=768, C=6, nhops=2
#define NC  6
#define LL  128
#define KP  1600     // padded K (1554 -> 1600)
#define MP  640      // padded M (513 -> 640)
#define NF  1536     // output feature width

typedef unsigned int u32;
typedef unsigned short u16;

// Scratch (allocation-free: __device__ globals)
__device__ __align__(16) __nv_bfloat16 g_A[2][2][MP * KP];   // [set][hi/lo], row-major [MP][KP]
__device__ __align__(16) __nv_bfloat16 g_Wt[2][NF * KP];     // [hi/lo], W^T: row n, col k
__device__ __align__(16) float g_clsT[NC * 1536];
__device__ float g_pqr2[2][513 * NC];       // ping-pong: 0..255 p, 256..511 q, 512 r
__device__ float g_pp[48 * MP * NC];        // per-(nCTA,wn) probs partials
__device__ float g_pooled[2 * LL * NC];

__device__ __forceinline__ void bsplit(float v, u16& h, u16& l) {
    __nv_bfloat16 hb = __float2bfloat16(v);
    __nv_bfloat16 lb = __float2bfloat16(v - __bfloat162float(hb));
    h = *(u16*)&hb; l = *(u16*)&lb;
}
__device__ __forceinline__ u32 smem_u32(const void* p) {
    u32 a;
    asm("{ .reg .u64 t; cvta.to.shared.u64 t, %1; cvt.u32.u64 %0, t; }" : "=r"(a) : "l"(p));
    return a;
}
__device__ __forceinline__ void cpa16(u32 s, const void* g) {
    asm volatile("cp.async.cg.shared.global [%0], [%1], 16;" :: "r"(s), "l"(g));
}
__device__ __forceinline__ u32 lds32(u32 a) {
    u32 x; asm volatile("ld.shared.b32 %0, [%1];" : "=r"(x) : "r"(a)); return x;
}
__device__ __forceinline__ void mma16816(float* c, const u32* a, u32 b0, u32 b1) {
    asm volatile("mma.sync.aligned.m16n8k16.row.col.f32.bf16.bf16.f32 "
        "{%0,%1,%2,%3},{%4,%5,%6,%7},{%8,%9},{%0,%1,%2,%3};"
        : "+f"(c[0]), "+f"(c[1]), "+f"(c[2]), "+f"(c[3])
        : "r"(a[0]), "r"(a[1]), "r"(a[2]), "r"(a[3]), "r"(b0), "r"(b1));
}

// ---------------- one-time: transpose+split feat_w -> g_Wt ----------------
__global__ void k_convW(const float* __restrict__ feat_w) {
    __shared__ float ts[32][33];
    int bk = blockIdx.x, bn = blockIdx.y;            // k tile 0..49, n tile 0..47
    int tx = threadIdx.x, ty = threadIdx.y;          // 32 x 8
    #pragma unroll
    for (int i = 0; i < 32; i += 8) {
        int k = bk * 32 + ty + i;
        ts[ty + i][tx] = (k < 1554) ? feat_w[(size_t)k * 1536 + bn * 32 + tx] : 0.f;
    }
    __syncthreads();
    #pragma unroll
    for (int i = 0; i < 32; i += 8) {
        int n = bn * 32 + ty + i;
        int k = bk * 32 + tx;
        u16 h, l; bsplit(ts[tx][ty + i], h, l);
        *(u16*)&g_Wt[0][(size_t)n * KP + k] = h;
        *(u16*)&g_Wt[1][(size_t)n * KP + k] = l;
    }
}

// ---------------- one-time: transposed cls_w ----------------
__global__ void k_cls(const float* __restrict__ cls_w) {
    int t = blockIdx.x * 256 + threadIdx.x;
    if (t < NC * 1536) {
        int c = t / 1536, k = t % 1536;
        g_clsT[t] = cls_w[k * NC + c];
    }
}

// ---------------- init: A set0 bf16 hi/lo (+ zero pad rows of set1) ----------------
__global__ void k_init(const float* __restrict__ hidden) {
    int row = blockIdx.x;                            // 0..639
    for (int c = threadIdx.x; c < KP; c += 256) {
        float v = 0.f;
        if (row < 256)      { if (c < 768) v = hidden[row * 768 + c]; }
        else if (row < 512) { if (c >= 768 && c < 1536) v = hidden[(row - 256) * 768 + c - 768]; }
        u16 h, l; bsplit(v, h, l);
        *(u16*)&g_A[0][0][(size_t)row * KP + c] = h;
        *(u16*)&g_A[0][1][(size_t)row * KP + c] = l;
        if (row >= 513) {                            // pad rows of set1 stay zero forever
            *(u16*)&g_A[1][0][(size_t)row * KP + c] = 0;
            *(u16*)&g_A[1][1][(size_t)row * KP + c] = 0;
        }
    }
}

// ---------------- probs0 directly from hidden ----------------
__global__ void k_probs0(const float* __restrict__ hidden, const float* __restrict__ cls_b) {
    int row  = blockIdx.x;                           // 0..255
    int warp = threadIdx.x >> 5, lane = threadIdx.x & 31;  // 6 warps
    const float4* hr = (const float4*)(hidden + (size_t)row * 768);
    const float4* w0 = (const float4*)(g_clsT + warp * 1536);
    const float4* w1 = (const float4*)(g_clsT + warp * 1536 + 768);
    float sp = 0.f, sq = 0.f;
    #pragma unroll
    for (int it = 0; it < 6; it++) {                 // 6*32*4 = 768
        int k4 = it * 32 + lane;
        float4 a = hr[k4], b = w0[k4], c = w1[k4];
        sp += a.x * b.x + a.y * b.y + a.z * b.z + a.w * b.w;
        sq += a.x * c.x + a.y * c.y + a.z * c.z + a.w * c.w;
    }
    #pragma unroll
    for (int o = 16; o; o >>= 1) {
        sp += __shfl_down_sync(0xffffffffu, sp, o);
        sq += __shfl_down_sync(0xffffffffu, sq, o);
    }
    if (lane == 0) {
        g_pqr2[0][row * NC + warp] = sp;
        g_pqr2[0][(256 + row) * NC + warp] = sq;
        if (row == 0) g_pqr2[0][512 * NC + warp] = cls_b[warp];
    }
}

// ---------------- exact masked max-pool on separable probs ----------------
__global__ void k_pool(const float* __restrict__ am, int src) {
    int b = blockIdx.x / NC, c = blockIdx.x % NC;    // 12 blocks
    __shared__ float sp[LL], sq[LL], sm[LL];
    const float* pqr = g_pqr2[src];
    int k = threadIdx.x;                             // 128 threads
    sp[k] = pqr[(b * LL + k) * NC + c];
    sq[k] = pqr[(256 + b * LL + k) * NC + c];
    sm[k] = am[b * LL + k];
    __syncthreads();
    float r  = pqr[512 * NC + c];
    float mk = sm[k], pk = sp[k], qk = sq[k];
    float mx = -INFINITY;
    #pragma unroll 4
    for (int i = 0; i < LL; i++) {
        float mi  = sm[i];
        float mv1 = (i <= k) ? mi * mk : 0.f;        // column k over i
        mx = fmaxf(mx, (sp[i] + qk + r) * mv1);
        float mv2 = (i >= k) ? mk * mi : 0.f;        // row k over j
        mx = fmaxf(mx, (pk + sq[i] + r) * mv2);
    }
    g_pooled[(b * LL + k) * NC + c] = mx;
}

// ---------------- per-hop: fill ext cols 1536..1599 of A[set], rows 0..512 ----------------
__global__ void k_ext(int set, int src) {
    int idx = blockIdx.x * 256 + threadIdx.x;
    if (idx >= 513 * 64) return;
    int row = idx >> 6, cc = idx & 63;
    float v = 0.f;
    if (cc < 6)       { if (row < 256) v = g_pooled[row * NC + cc]; }
    else if (cc < 12) { if (row >= 256 && row < 512) v = g_pooled[(row - 256) * NC + cc - 6]; }
    else if (cc < 18) v = g_pqr2[src][row * NC + cc - 12];
    u16 h, l; bsplit(v, h, l);
    *(u16*)&g_A[set][0][(size_t)row * KP + 1536 + cc] = h;
    *(u16*)&g_A[set][1][(size_t)row * KP + 1536 + cc] = l;
}

// ---------------- HMMA split-bf16 GEMM, fused probs epilogue ----------------
// CTA 128x64, 8 warps (4m x 2n, warp tile 32x32), 3-stage cp.async pipeline.
// Emits next hop's bf16 hi/lo A + per-slab probs partials (no fp32 C at all).
#define STG 30720     // Ah 10240 | Al 10240 | Bh 5120 | Bl 5120   (pitch 80B)
__global__ void __launch_bounds__(256, 1) k_gemm(int set, const float* __restrict__ bias) {
    extern __shared__ __align__(16) char smem[];
    const __nv_bfloat16* Ah = g_A[set][0];
    const __nv_bfloat16* Al = g_A[set][1];
    __nv_bfloat16* Aoh = g_A[set ^ 1][0];
    __nv_bfloat16* Aol = g_A[set ^ 1][1];

    const int tid = threadIdx.x;
    const int m0 = blockIdx.y * 128, n0 = blockIdx.x * 64;
    const u32 sb = smem_u32(smem);

    const int r4 = tid >> 2, q4 = (tid & 3) * 16;    // copy row/chunk
    const char* gAh = (const char*)Ah + (size_t)(m0 + r4) * (KP * 2) + q4;
    const char* gAl = (const char*)Al + (size_t)(m0 + r4) * (KP * 2) + q4;
    const char* gBh = (const char*)g_Wt[0] + (size_t)(n0 + r4) * (KP * 2) + q4;
    const char* gBl = (const char*)g_Wt[1] + (size_t)(n0 + r4) * (KP * 2) + q4;

    #define COPY_STAGE(s, kt) do {                                            \
        u32 d = sb + (s) * STG;                                               \
        int kb = (kt) * 64;                                                   \
        cpa16(d +         r4 * 80 + q4,        gAh + kb);                     \
        cpa16(d +         (64 + r4) * 80 + q4, gAh + kb + 64 * KP * 2);       \
        cpa16(d + 10240 + r4 * 80 + q4,        gAl + kb);                     \
        cpa16(d + 10240 + (64 + r4) * 80 + q4, gAl + kb + 64 * KP * 2);       \
        cpa16(d + 20480 + r4 * 80 + q4,        gBh + kb);                     \
        cpa16(d + 25600 + r4 * 80 + q4,        gBl + kb);                     \
        asm volatile("cp.async.commit_group;" ::: "memory");                  \
    } while (0)

    COPY_STAGE(0, 0);
    COPY_STAGE(1, 1);

    const int wid = tid >> 5, lane = tid & 31;
    const int wm = wid & 3, wn = wid >> 2;           // warp grid 4(m) x 2(n)
    const int g = lane >> 2, t = lane & 3;
    const u32 a_off = (u32)((wm * 32 + g) * 80 + t * 4);
    const u32 b_off = (u32)(20480 + (wn * 32 + g) * 80 + t * 4);

    float acc[2][4][4];
    #pragma unroll
    for (int mt = 0; mt < 2; mt++)
        #pragma unroll
        for (int nt = 0; nt < 4; nt++)
            #pragma unroll
            for (int i = 0; i < 4; i++) acc[mt][nt][i] = 0.f;

    for (int kt = 0; kt < 50; kt++) {
        if (kt < 49) asm volatile("cp.async.wait_group 1;" ::: "memory");
        else         asm volatile("cp.async.wait_group 0;" ::: "memory");
        __syncthreads();
        u32 st = sb + (kt % 3) * STG;
        #pragma unroll
        for (int kk = 0; kk < 2; kk++) {             // two k16 halves (32B each)
            u32 ka = st + a_off + kk * 32;
            u32 kb = st + b_off + kk * 32;
            u32 ah[2][4], al[2][4];
            #pragma unroll
            for (int mt = 0; mt < 2; mt++) {
                u32 base = ka + mt * 1280;           // 16 rows * 80B
                ah[mt][0] = lds32(base);
                ah[mt][1] = lds32(base + 640);       // +8 rows
                ah[mt][2] = lds32(base + 16);        // +8 k
                ah[mt][3] = lds32(base + 656);
                al[mt][0] = lds32(base + 10240);
                al[mt][1] = lds32(base + 10880);
                al[mt][2] = lds32(base + 10256);
                al[mt][3] = lds32(base + 10896);
            }
            #pragma unroll
            for (int nt = 0; nt < 4; nt++) {
                u32 bb  = kb + nt * 640;             // +8 n rows
                u32 bh0 = lds32(bb),        bh1 = lds32(bb + 16);
                u32 bl0 = lds32(bb + 5120), bl1 = lds32(bb + 5136);
                #pragma unroll
                for (int mt = 0; mt < 2; mt++) {
                    mma16816(acc[mt][nt], ah[mt], bh0, bh1);
                    mma16816(acc[mt][nt], ah[mt], bl0, bl1);
                    mma16816(acc[mt][nt], al[mt], bh0, bh1);
                }
            }
        }
        if (kt + 2 < 50) COPY_STAGE((kt + 2) % 3, kt + 2);
    }

    // ---- epilogue ----
    // bias pre-pass on the constant row (512)
    #pragma unroll
    for (int mt = 0; mt < 2; mt++)
        #pragma unroll
        for (int half = 0; half < 2; half++) {
            int r = m0 + wm * 32 + mt * 16 + g + half * 8;
            if (r == 512) {
                #pragma unroll
                for (int nt = 0; nt < 4; nt++) {
                    int col = n0 + wn * 32 + nt * 8 + t * 2;
                    acc[mt][nt][half * 2]     += bias[col];
                    acc[mt][nt][half * 2 + 1] += bias[col + 1];
                }
            }
        }

    // next-hop bf16 hi/lo A
    #pragma unroll
    for (int mt = 0; mt < 2; mt++)
        #pragma unroll
        for (int nt = 0; nt < 4; nt++) {
            int col = n0 + wn * 32 + nt * 8 + t * 2;
            #pragma unroll
            for (int half = 0; half < 2; half++) {
                int r = m0 + wm * 32 + mt * 16 + g + half * 8;
                if (r < 513) {
                    u16 h0, l0, h1, l1;
                    bsplit(acc[mt][nt][half * 2], h0, l0);
                    bsplit(acc[mt][nt][half * 2 + 1], h1, l1);
                    *(u32*)(Aoh + (size_t)r * KP + col) = (u32)h0 | ((u32)h1 << 16);
                    *(u32*)(Aol + (size_t)r * KP + col) = (u32)l0 | ((u32)l1 << 16);
                }
            }
        }

    // probs partials: part[r][c] = sum over this warp's 32 cols of C[r,col]*clsT[c][col]
    float* pp = g_pp + (size_t)(blockIdx.x * 2 + wn) * (MP * NC);
    #pragma unroll
    for (int c = 0; c < NC; c++) {
        float cv[4][2];
        #pragma unroll
        for (int nt = 0; nt < 4; nt++) {
            int col = n0 + wn * 32 + nt * 8 + t * 2;
            cv[nt][0] = g_clsT[c * 1536 + col];
            cv[nt][1] = g_clsT[c * 1536 + col + 1];
        }
        #pragma unroll
        for (int mt = 0; mt < 2; mt++)
            #pragma unroll
            for (int half = 0; half < 2; half++) {
                float s = 0.f;
                #pragma unroll
                for (int nt = 0; nt < 4; nt++)
                    s += acc[mt][nt][half * 2] * cv[nt][0]
                       + acc[mt][nt][half * 2 + 1] * cv[nt][1];
                s += __shfl_xor_sync(0xffffffffu, s, 1);
                s += __shfl_xor_sync(0xffffffffu, s, 2);
                if (t == 0) {
                    int r = m0 + wm * 32 + mt * 16 + g + half * 8;
                    if (r < 513) pp[r * NC + c] = s;
                }
            }
    }
    #undef COPY_STAGE
}

// ---------------- reduce probs partials: pqr2[dst] = sum over 48 slabs ----------------
__global__ void k_red(int dst, const float* __restrict__ cls_b) {
    int gw = blockIdx.x * 8 + (threadIdx.x >> 5);    // 0..3077
    int lane = threadIdx.x & 31;
    if (gw >= 513 * NC) return;
    int row = gw / NC, c = gw % NC;
    float s = g_pp[(size_t)lane * (MP * NC) + row * NC + c]
            + g_pp[(size_t)(lane + 32) * (MP * NC) + ((lane + 32) < 48 ? row * NC + c : 0)] * ((lane + 32) < 48 ? 1.f : 0.f);
    #pragma unroll
    for (int o = 16; o; o >>= 1) s += __shfl_down_sync(0xffffffffu, s, o);
    if (lane == 0) {
        if (row == 512) s += cls_b[c];
        g_pqr2[dst][row * NC + c] = s;
    }
}

// ---------------- final: logits[b,i,j,c] = p[b,i,c] + q[b,j,c] + r[c] ----------------
__global__ void k_out(float* __restrict__ out) {
    int idx = blockIdx.x * 256 + threadIdx.x;        // 0..196607 exact
    int c = idx % NC;
    int j = (idx / NC) % LL;
    int t = idx / (NC * LL);
    int i = t % LL;
    int b = t / LL;
    const float* pqr = g_pqr2[0];
    out[idx] = pqr[(b * LL + i) * NC + c]
             + pqr[(256 + b * LL + j) * NC + c]
             + pqr[512 * NC + c];
}

extern "C" void kernel_launch(void* const* d_in, const int* in_sizes, int n_in,
                              void* d_out, int out_size) {
    const float* hidden = (const float*)d_in[0];
    const float* am     = (const float*)d_in[1];
    const float* cls_w  = (const float*)d_in[2];
    const float* cls_b  = (const float*)d_in[3];
    const float* feat_w = (const float*)d_in[4];
    const float* feat_b = (const float*)d_in[5];

    cudaFuncSetAttribute(k_gemm, cudaFuncAttributeMaxDynamicSharedMemorySize, 3 * STG);

    k_convW<<<dim3(50, 48), dim3(32, 8)>>>(feat_w);
    k_cls<<<36, 256>>>(cls_w);
    k_init<<<MP, 256>>>(hidden);
    k_probs0<<<256, 192>>>(hidden, cls_b);

    for (int h = 0; h < 2; h++) {
        int set = h, src = h, dst = h ^ 1;
        k_pool<<<12, 128>>>(am, src);
        k_ext<<<129, 256>>>(set, src);
        k_gemm<<<dim3(24, 5), 256, 3 * STG>>>(set, feat_b);
        k_red<<<385, 256>>>(dst, cls_b);
    }
    k_out<<<768, 256>>>((float*)d_out);
}